// round 6
// baseline (speedup 1.0000x reference)
#include <cuda_runtime.h>
#include <cstdint>

#define NPTS   65536
#define NQ     1024
#define NBATCH 2
#define NS1    32
#define NS2    64
#define NOUT   128
#define NG     (NPTS / 32)          // 2048 mask words per query per radius
#define DPRE   16384                // prefix depth
#define NGP    (DPRE / 32)          // 512 prefix words
#define NTILES_TAIL ((NPTS - DPRE) / 1024)   // 48

static __device__ float4   g_pts4[NBATCH * NPTS];        // (x,y,z,|p|^2)
static __device__ unsigned g_mask1[NBATCH * NQ * NG];    // r1 hit bits
static __device__ unsigned g_mask2[NBATCH * NQ * NG];    // r2 hit bits
static __device__ int      g_lists[NBATCH * NQ * 96];    // [l1(32)|l2(64)]
static __device__ int      g_filled[NBATCH * NQ];
static __device__ int      g_unf[NBATCH][NQ];
static __device__ int      g_unf_cnt[NBATCH];

__device__ __forceinline__ float sq3_rn(float x, float y, float z) {
    return __fadd_rn(__fadd_rn(__fmul_rn(x, x), __fmul_rn(y, y)), __fmul_rn(z, z));
}

__device__ __forceinline__ int query_flat_index(int q, int& b) {
    b = q >> 10;
    const int m = q & 1023;
    return (4 + 8 * (m >> 5)) * 256 + (4 + 8 * (m & 31));
}

__device__ __forceinline__ void radii(float& r1sq, float& r2sq) {
    r1sq = __fmul_rn(0.1f, 0.1f);
    r2sq = __fmul_rn(0.2f, 0.2f);
}

// d2 with the exact rounding order of the reference (and all prior passing rounds)
__device__ __forceinline__ float dist2_rn(float4 pt, float qx, float qy, float qz, float q2) {
    const float dot = __fadd_rn(__fadd_rn(__fmul_rn(pt.x, qx), __fmul_rn(pt.y, qy)),
                                __fmul_rn(pt.z, qz));
    return __fadd_rn(__fadd_rn(q2, pt.w), __fmul_rn(-2.0f, dot));
}

// ---------------------------------------------------------------------------
// Kernel 0: pack pts -> float4(x,y,z,|p|^2); reset unfilled counters.
// ---------------------------------------------------------------------------
__global__ __launch_bounds__(256) void prep_kernel(const float* __restrict__ pts) {
    const int i = blockIdx.x * 256 + threadIdx.x;   // 0 .. 131071
    const float x = __ldg(pts + 3 * i + 0);
    const float y = __ldg(pts + 3 * i + 1);
    const float z = __ldg(pts + 3 * i + 2);
    g_pts4[i] = make_float4(x, y, z, sq3_rn(x, y, z));
    if (i < NBATCH) g_unf_cnt[i] = 0;
}

// ---------------------------------------------------------------------------
// Kernel 1: prefix masks. Block = 256 threads, 16 queries, one 1024-pt tile.
// Grid = 16 tiles x 128 query-blocks (tile-major for L2 sharing).
// Warp handles 2 queries over the staged tile; lane = point; ballots -> words.
// ---------------------------------------------------------------------------
__global__ __launch_bounds__(256) void mask_prefix_kernel() {
    __shared__ float4 s_p[1024];

    const int bid  = blockIdx.x;
    const int qblk = bid & 127;         // 0..127 (16 queries each)
    const int tile = bid >> 7;          // 0..15
    const int tid  = threadIdx.x;
    const int lane = tid & 31;
    const int wid  = tid >> 5;

    const int b = qblk >> 6;            // batch (uniform per block)
    const float4* __restrict__ P4 = g_pts4 + (size_t)b * NPTS;
    const int pbase = tile * 1024;

#pragma unroll
    for (int j = 0; j < 4; j++) s_p[tid + j * 256] = __ldg(P4 + pbase + tid + j * 256);

    const int qA = qblk * 16 + wid * 2;
    const int qB = qA + 1;
    int bb;
    const float4 qpA = __ldg(P4 + query_flat_index(qA, bb));
    const float4 qpB = __ldg(P4 + query_flat_index(qB, bb));
    float r1sq, r2sq; radii(r1sq, r2sq);

    __syncthreads();

    unsigned* m1A = g_mask1 + (size_t)qA * NG + tile * 32;
    unsigned* m2A = g_mask2 + (size_t)qA * NG + tile * 32;
    unsigned* m1B = g_mask1 + (size_t)qB * NG + tile * 32;
    unsigned* m2B = g_mask2 + (size_t)qB * NG + tile * 32;

#pragma unroll 8
    for (int g = 0; g < 32; g++) {
        const float4 pt = s_p[g * 32 + lane];
        const float dA = dist2_rn(pt, qpA.x, qpA.y, qpA.z, qpA.w);
        const float dB = dist2_rn(pt, qpB.x, qpB.y, qpB.z, qpB.w);
        const unsigned w1A = __ballot_sync(0xffffffffu, dA < r1sq);
        const unsigned w2A = __ballot_sync(0xffffffffu, dA < r2sq);
        const unsigned w1B = __ballot_sync(0xffffffffu, dB < r1sq);
        const unsigned w2B = __ballot_sync(0xffffffffu, dB < r2sq);
        if (lane == 0) {
            m1A[g] = w1A; m2A[g] = w2A;
            m1B[g] = w1B; m2B[g] = w2B;
        }
    }
}

// ---------------------------------------------------------------------------
// Extract the first K set-bit indices (ascending) from nwords mask words.
// Warp-collective; returns total count seen up to the stopping chunk.
// ---------------------------------------------------------------------------
__device__ __forceinline__ int extract_list(
    const unsigned* __restrict__ mask, int nwords, int K, int lane, int* __restrict__ list)
{
    int cnt = 0;
    for (int w0 = 0; w0 < nwords && cnt < K; w0 += 32) {
        const unsigned v = mask[w0 + lane];
        const int pc = __popc(v);
        int pre = pc;   // inclusive scan
#pragma unroll
        for (int d = 1; d < 32; d <<= 1) {
            const int t = __shfl_up_sync(0xffffffffu, pre, d);
            if (lane >= d) pre += t;
        }
        const int base = cnt + (pre - pc);
        unsigned vv = v; int k = 0;
        while (vv) {
            const int bit = __ffs(vv) - 1;
            const int p = base + k;
            if (p < K) list[p] = (w0 + lane) * 32 + bit;
            k++; vv &= vv - 1;
        }
        cnt += __shfl_sync(0xffffffffu, pre, 31);
    }
    return cnt;
}

__device__ __forceinline__ void write_lists_padded(
    int q, int lane, const int* __restrict__ l1, int c1, const int* __restrict__ l2, int c2)
{
    int* g1 = g_lists + q * 96;
    int* g2 = g1 + NS1;
    const int n1 = min(c1, NS1), n2 = min(c2, NS2);
    const int f1 = (n1 > 0) ? l1[0] : 0;
    const int f2 = (n2 > 0) ? l2[0] : 0;
    if (lane < NS1) g1[lane] = (lane < n1) ? l1[lane] : f1;
#pragma unroll
    for (int j = 0; j < 2; j++) {
        const int i = lane + j * 32;
        g2[i] = (i < n2) ? l2[i] : f2;
    }
}

// ---------------------------------------------------------------------------
// Kernel 2: extract from prefix masks; queue unfilled queries.
// ---------------------------------------------------------------------------
__global__ __launch_bounds__(256) void extract1_kernel() {
    __shared__ int ll1[8][NS1];
    __shared__ int ll2[8][NS2];

    const int lane = threadIdx.x & 31;
    const int wid  = threadIdx.x >> 5;
    const int q    = blockIdx.x * 8 + wid;
    const int b    = q >> 10;

    const int c1 = extract_list(g_mask1 + (size_t)q * NG, NGP, NS1, lane, ll1[wid]);
    const int c2 = extract_list(g_mask2 + (size_t)q * NG, NGP, NS2, lane, ll2[wid]);
    __syncwarp();

    const bool filled = (c1 >= NS1) && (c2 >= NS2);
    if (filled) {
        write_lists_padded(q, lane, ll1[wid], c1, ll2[wid], c2);
        if (lane == 0) g_filled[q] = 1;
    } else {
        if (lane == 0) {
            g_filled[q] = 0;
            const int pos = atomicAdd(&g_unf_cnt[b], 1);
            g_unf[b][pos] = q;
        }
    }
}

// ---------------------------------------------------------------------------
// Kernel 3: tail masks for unfilled queries. 4 queries per block; block stages
// 48 x 1024-pt tiles of [DPRE, NPTS); warp handles 4 groups x 4 query slots.
// Grid = NBATCH * 256 blocks.
// ---------------------------------------------------------------------------
__global__ __launch_bounds__(256) void mask_tail_kernel() {
    __shared__ float4 s_p[1024];

    const int bid   = blockIdx.x;
    const int b     = bid >> 8;
    const int i4    = bid & 255;
    const int nb    = g_unf_cnt[b];
    if (i4 * 4 >= nb) return;

    const int tid  = threadIdx.x;
    const int lane = tid & 31;
    const int wid  = tid >> 5;

    int   qs[4];
    bool  vs[4];
    float4 qp[4];
    int bb;
#pragma unroll
    for (int s = 0; s < 4; s++) {
        const int u = i4 * 4 + s;
        vs[s] = (u < nb);
        qs[s] = vs[s] ? g_unf[b][u] : 0;
        qp[s] = vs[s] ? __ldg(g_pts4 + (size_t)b * NPTS + query_flat_index(qs[s], bb))
                      : make_float4(0, 0, 0, 0);
    }
    float r1sq, r2sq; radii(r1sq, r2sq);

    const float4* __restrict__ P4 = g_pts4 + (size_t)b * NPTS;

    for (int t = 0; t < NTILES_TAIL; t++) {
        const int pbase = DPRE + t * 1024;
#pragma unroll
        for (int j = 0; j < 4; j++) s_p[tid + j * 256] = __ldg(P4 + pbase + tid + j * 256);
        __syncthreads();

        // warp handles groups [wid*4, wid*4+4) for each valid slot
#pragma unroll
        for (int gg = 0; gg < 4; gg++) {
            const int g = wid * 4 + gg;
            const float4 pt = s_p[g * 32 + lane];
            const int word = (pbase >> 5) + g;
#pragma unroll
            for (int s = 0; s < 4; s++) {
                if (vs[s]) {
                    const float d = dist2_rn(pt, qp[s].x, qp[s].y, qp[s].z, qp[s].w);
                    const unsigned w1 = __ballot_sync(0xffffffffu, d < r1sq);
                    const unsigned w2 = __ballot_sync(0xffffffffu, d < r2sq);
                    if (lane == 0) {
                        g_mask1[(size_t)qs[s] * NG + word] = w1;
                        g_mask2[(size_t)qs[s] * NG + word] = w2;
                    }
                }
            }
        }
        __syncthreads();
    }
}

// ---------------------------------------------------------------------------
// Kernel 4: extract over full mask range for unfilled queries (with padding).
// ---------------------------------------------------------------------------
__global__ __launch_bounds__(256) void extract2_kernel() {
    __shared__ int ll1[8][NS1];
    __shared__ int ll2[8][NS2];

    const int lane = threadIdx.x & 31;
    const int wid  = threadIdx.x >> 5;
    const int q    = blockIdx.x * 8 + wid;
    if (g_filled[q]) return;

    const int c1 = extract_list(g_mask1 + (size_t)q * NG, NG, NS1, lane, ll1[wid]);
    const int c2 = extract_list(g_mask2 + (size_t)q * NG, NG, NS2, lane, ll2[wid]);
    __syncwarp();
    write_lists_padded(q, lane, ll1[wid], c1, ll2[wid], c2);
}

// ---------------------------------------------------------------------------
// Kernel 5: MLP (R3 version — 104 regs, 20.5us measured).
// ---------------------------------------------------------------------------
#define INVC 0.9999950000374997f

__device__ __forceinline__ void mlp_point(
    float gx, float gy, float gz, float qx, float qy, float qz,
    const float* __restrict__ sA, const float* __restrict__ scA, const float* __restrict__ biA,
    const float* __restrict__ sB, const float* __restrict__ scB, const float* __restrict__ biB,
    float f[32])
{
    const float x0 = gx - qx, x1 = gy - qy, x2 = gz - qz;
    float a[16];
#pragma unroll
    for (int o = 0; o < 16; o++) {
        const float* w = sA + o * 6;
        float y = x0 * w[0];
        y = fmaf(x1, w[1], y);
        y = fmaf(x2, w[2], y);
        y = fmaf(gx, w[3], y);
        y = fmaf(gy, w[4], y);
        y = fmaf(gz, w[5], y);
        a[o] = fmaxf(fmaf(y, scA[o], biA[o]), 0.0f);
    }
#pragma unroll
    for (int o = 0; o < 32; o++) {
        const float* w = sB + o * 16;
        float y = 0.0f;
#pragma unroll
        for (int c = 0; c < 16; c++) y = fmaf(a[c], w[c], y);
        f[o] = fmaxf(f[o], fmaxf(fmaf(y, scB[o], biB[o]), 0.0f));
    }
}

__device__ __forceinline__ void warp_max32(float f[32]) {
#pragma unroll
    for (int o = 0; o < 32; o++) {
        float v = f[o];
        v = fmaxf(v, __shfl_xor_sync(0xffffffffu, v, 16));
        v = fmaxf(v, __shfl_xor_sync(0xffffffffu, v, 8));
        v = fmaxf(v, __shfl_xor_sync(0xffffffffu, v, 4));
        v = fmaxf(v, __shfl_xor_sync(0xffffffffu, v, 2));
        v = fmaxf(v, __shfl_xor_sync(0xffffffffu, v, 1));
        f[o] = v;
    }
}

__global__ __launch_bounds__(256) void mlp_kernel(
    const float* __restrict__ w1a, const float* __restrict__ g1a, const float* __restrict__ b1a,
    const float* __restrict__ w1b, const float* __restrict__ g1b, const float* __restrict__ b1b,
    const float* __restrict__ w2a, const float* __restrict__ g2a, const float* __restrict__ b2a,
    const float* __restrict__ w2b, const float* __restrict__ g2b, const float* __restrict__ b2b,
    const float* __restrict__ w3,  const float* __restrict__ b3,
    float* __restrict__ out)
{
    __shared__ float s_w1a[96],  s_w2a[96];
    __shared__ float s_w1b[512], s_w2b[512];
    __shared__ float s_sc1a[16], s_bi1a[16], s_sc2a[16], s_bi2a[16];
    __shared__ float s_sc1b[32], s_bi1b[32], s_sc2b[32], s_bi2b[32];
    __shared__ float s_w3t[64 * 129];

    const int tid = threadIdx.x;
    for (int i = tid; i < 96; i += 256)  { s_w1a[i] = w1a[i]; s_w2a[i] = w2a[i]; }
    for (int i = tid; i < 512; i += 256) { s_w1b[i] = w1b[i]; s_w2b[i] = w2b[i]; }
    if (tid < 16) {
        s_sc1a[tid] = g1a[tid] * INVC; s_bi1a[tid] = b1a[tid];
        s_sc2a[tid] = g2a[tid] * INVC; s_bi2a[tid] = b2a[tid];
    } else if (tid < 48) {
        const int i = tid - 16;
        s_sc1b[i] = g1b[i] * INVC; s_bi1b[i] = b1b[i];
        s_sc2b[i] = g2b[i] * INVC; s_bi2b[i] = b2b[i];
    }
    const float4* __restrict__ w3v = (const float4*)w3;
    for (int i = tid; i < NOUT * 16; i += 256) {
        const float4 v = __ldg(w3v + i);
        const int o  = i >> 4;
        const int c4 = (i & 15) * 4;
        s_w3t[(c4 + 0) * 129 + o] = v.x;
        s_w3t[(c4 + 1) * 129 + o] = v.y;
        s_w3t[(c4 + 2) * 129 + o] = v.z;
        s_w3t[(c4 + 3) * 129 + o] = v.w;
    }
    __syncthreads();

    const int lane = tid & 31;
    const int wid  = tid >> 5;
    const int q    = blockIdx.x * 8 + wid;
    int b;
    const int fi = query_flat_index(q, b);

    const float4* __restrict__ P4 = g_pts4 + (size_t)b * NPTS;
    const float4 qp = __ldg(P4 + fi);
    const float qx = qp.x, qy = qp.y, qz = qp.z;

    const int* lst = g_lists + q * 96;
    const int i0 = __ldg(lst + lane);
    const int i1 = __ldg(lst + NS1 + lane);
    const int i2 = __ldg(lst + NS1 + 32 + lane);
    const float4 n0 = __ldg(P4 + i0);
    const float4 n1 = __ldg(P4 + i1);
    const float4 n2 = __ldg(P4 + i2);

    const size_t ob = (size_t)q * NOUT;
    float acc[4];
#pragma unroll
    for (int k = 0; k < 4; k++) acc[k] = __ldg(b3 + lane + 32 * k);

    {   // branch 1 (S=32)
        float f[32];
#pragma unroll
        for (int o = 0; o < 32; o++) f[o] = 0.0f;
        mlp_point(n0.x, n0.y, n0.z, qx, qy, qz, s_w1a, s_sc1a, s_bi1a, s_w1b, s_sc1b, s_bi1b, f);
        warp_max32(f);
#pragma unroll
        for (int k = 0; k < 4; k++) {
            const int o = lane + 32 * k;
            float a = acc[k];
#pragma unroll
            for (int c = 0; c < 32; c++) a = fmaf(f[c], s_w3t[c * 129 + o], a);
            acc[k] = a;
        }
    }
    {   // branch 2 (S=64)
        float f[32];
#pragma unroll
        for (int o = 0; o < 32; o++) f[o] = 0.0f;
        mlp_point(n1.x, n1.y, n1.z, qx, qy, qz, s_w2a, s_sc2a, s_bi2a, s_w2b, s_sc2b, s_bi2b, f);
        mlp_point(n2.x, n2.y, n2.z, qx, qy, qz, s_w2a, s_sc2a, s_bi2a, s_w2b, s_sc2b, s_bi2b, f);
        warp_max32(f);
#pragma unroll
        for (int k = 0; k < 4; k++) {
            const int o = lane + 32 * k;
            float a = acc[k];
#pragma unroll
            for (int c = 0; c < 32; c++) a = fmaf(f[c], s_w3t[(c + 32) * 129 + o], a);
            acc[k] = a;
        }
    }
#pragma unroll
    for (int k = 0; k < 4; k++) out[ob + lane + 32 * k] = acc[k];
}

extern "C" void kernel_launch(void* const* d_in, const int* in_sizes, int n_in,
                              void* d_out, int out_size) {
    const float* pts = (const float*)d_in[0];
    const float* w1a = (const float*)d_in[1];
    const float* g1a = (const float*)d_in[2];
    const float* b1a = (const float*)d_in[3];
    const float* w1b = (const float*)d_in[4];
    const float* g1b = (const float*)d_in[5];
    const float* b1b = (const float*)d_in[6];
    const float* w2a = (const float*)d_in[7];
    const float* g2a = (const float*)d_in[8];
    const float* b2a = (const float*)d_in[9];
    const float* w2b = (const float*)d_in[10];
    const float* g2b = (const float*)d_in[11];
    const float* b2b = (const float*)d_in[12];
    const float* w3  = (const float*)d_in[13];
    const float* b3  = (const float*)d_in[14];
    float* out = (float*)d_out;

    prep_kernel<<<NBATCH * NPTS / 256, 256>>>(pts);
    mask_prefix_kernel<<<16 * 128, 256>>>();
    extract1_kernel<<<NBATCH * NQ / 8, 256>>>();
    mask_tail_kernel<<<NBATCH * 256, 256>>>();
    extract2_kernel<<<NBATCH * NQ / 8, 256>>>();
    mlp_kernel<<<NBATCH * NQ / 8, 256>>>(w1a, g1a, b1a, w1b, g1b, b1b,
                                         w2a, g2a, b2a, w2b, g2b, b2b, w3, b3, out);
}

// round 8
// speedup vs baseline: 1.5322x; 1.5322x over previous
#include <cuda_runtime.h>
#include <cstdint>

#define NPTS   65536
#define NQ     1024
#define NBATCH 2
#define NS1    32
#define NS2    64
#define NOUT   128
#define NG     2048                 // mask words per query per radius
#define DPRE   16384                // prefix depth (points)
#define NGP    512                  // prefix words
#define NGT    (NG - NGP)           // 1536 tail words
#define WBLK_P (NGP / 16)           // 32 word-blocks, prefix
#define WBLK_T (NGT / 16)           // 96 word-blocks, tail
#define SLOTCAP 1024                // max unfilled per batch (full coverage)

static __device__ float4   g_pts4[NBATCH * NPTS];        // (x,y,z,|p|^2)
static __device__ unsigned g_mask1[(size_t)NBATCH * NQ * NG];
static __device__ unsigned g_mask2[(size_t)NBATCH * NQ * NG];
static __device__ int      g_lists[NBATCH * NQ * 96];    // [l1(32)|l2(64)]
static __device__ int      g_filled[NBATCH * NQ];
static __device__ int      g_unf[NBATCH][SLOTCAP];
static __device__ int      g_unf_cnt[NBATCH];

__device__ __forceinline__ float sq3_rn(float x, float y, float z) {
    return __fadd_rn(__fadd_rn(__fmul_rn(x, x), __fmul_rn(y, y)), __fmul_rn(z, z));
}

__device__ __forceinline__ int query_flat_index(int q, int& b) {
    b = q >> 10;
    const int m = q & 1023;
    return (4 + 8 * (m >> 5)) * 256 + (4 + 8 * (m & 31));
}

__device__ __forceinline__ void radii(float& r1sq, float& r2sq) {
    r1sq = __fmul_rn(0.1f, 0.1f);
    r2sq = __fmul_rn(0.2f, 0.2f);
}

// d2 with the exact rounding order of the reference.
__device__ __forceinline__ float dist2_rn(float4 pt, float qx, float qy, float qz, float q2) {
    const float dot = __fadd_rn(__fadd_rn(__fmul_rn(pt.x, qx), __fmul_rn(pt.y, qy)),
                                __fmul_rn(pt.z, qz));
    return __fadd_rn(__fadd_rn(q2, pt.w), __fmul_rn(-2.0f, dot));
}

// Ballot-free mask words for one (query, word): 32 points, predicated bit ORs.
__device__ __forceinline__ void make_mask_word(
    const float4* __restrict__ P4, int pbase, float4 qp,
    float r1sq, float r2sq, unsigned& m1, unsigned& m2)
{
    m1 = 0u; m2 = 0u;
#pragma unroll 8
    for (int i = 0; i < 32; i++) {
        const float4 p = __ldg(P4 + pbase + i);
        const float d2 = dist2_rn(p, qp.x, qp.y, qp.z, qp.w);
        m1 |= (d2 < r1sq) ? (1u << i) : 0u;
        m2 |= (d2 < r2sq) ? (1u << i) : 0u;
    }
}

// ---------------------------------------------------------------------------
// Kernel 0: pack pts -> float4(x,y,z,|p|^2); reset unfilled counters.
// ---------------------------------------------------------------------------
__global__ __launch_bounds__(256) void prep_kernel(const float* __restrict__ pts) {
    const int i = blockIdx.x * 256 + threadIdx.x;   // 0 .. 131071
    const float x = __ldg(pts + 3 * i + 0);
    const float y = __ldg(pts + 3 * i + 1);
    const float z = __ldg(pts + 3 * i + 2);
    g_pts4[i] = make_float4(x, y, z, sq3_rn(x, y, z));
    if (i < NBATCH) g_unf_cnt[i] = 0;
}

// ---------------------------------------------------------------------------
// Kernel 1: prefix masks, ballot-free. Block = 256 thr = 16 queries x 16 words.
// Lane layout: q = tid&15 (the 16 lanes sharing a word read identical point
// addresses -> LDG dedup/broadcast), word = tid>>4. Grid = 128 qblk x 32 wblk.
// ---------------------------------------------------------------------------
__global__ __launch_bounds__(256) void mask_prefix_kernel() {
    const int bid  = blockIdx.x;
    const int qblk = bid >> 5;          // 0..127
    const int wblk = bid & 31;          // 0..31
    const int tid  = threadIdx.x;

    const int q    = qblk * 16 + (tid & 15);
    const int word = wblk * 16 + (tid >> 4);
    int b;
    const int fi = query_flat_index(q, b);

    const float4* __restrict__ P4 = g_pts4 + (size_t)b * NPTS;
    const float4 qp = __ldg(P4 + fi);
    float r1sq, r2sq; radii(r1sq, r2sq);

    unsigned m1, m2;
    make_mask_word(P4, word * 32, qp, r1sq, r2sq, m1, m2);

    g_mask1[(size_t)q * NG + word] = m1;
    g_mask2[(size_t)q * NG + word] = m2;
}

// ---------------------------------------------------------------------------
// Extract the first K set-bit indices (ascending) from nwords mask words.
// Warp-collective; returns total count seen up to the stopping chunk.
// ---------------------------------------------------------------------------
__device__ __forceinline__ int extract_list(
    const unsigned* __restrict__ mask, int nwords, int K, int lane, int* __restrict__ list)
{
    int cnt = 0;
    for (int w0 = 0; w0 < nwords && cnt < K; w0 += 32) {
        const unsigned v = mask[w0 + lane];
        const int pc = __popc(v);
        int pre = pc;   // inclusive scan
#pragma unroll
        for (int d = 1; d < 32; d <<= 1) {
            const int t = __shfl_up_sync(0xffffffffu, pre, d);
            if (lane >= d) pre += t;
        }
        const int base = cnt + (pre - pc);
        unsigned vv = v; int k = 0;
        while (vv) {
            const int bit = __ffs(vv) - 1;
            const int p = base + k;
            if (p < K) list[p] = (w0 + lane) * 32 + bit;
            k++; vv &= vv - 1;
        }
        cnt += __shfl_sync(0xffffffffu, pre, 31);
    }
    return cnt;
}

__device__ __forceinline__ void write_lists_padded(
    int q, int lane, const int* __restrict__ l1, int c1, const int* __restrict__ l2, int c2)
{
    int* g1 = g_lists + q * 96;
    int* g2 = g1 + NS1;
    const int n1 = min(c1, NS1), n2 = min(c2, NS2);
    const int f1 = (n1 > 0) ? l1[0] : 0;
    const int f2 = (n2 > 0) ? l2[0] : 0;
    if (lane < NS1) g1[lane] = (lane < n1) ? l1[lane] : f1;
#pragma unroll
    for (int j = 0; j < 2; j++) {
        const int i = lane + j * 32;
        g2[i] = (i < n2) ? l2[i] : f2;
    }
}

// ---------------------------------------------------------------------------
// Kernel 2: extract from prefix masks; queue unfilled queries.
// ---------------------------------------------------------------------------
__global__ __launch_bounds__(256) void extract1_kernel() {
    __shared__ int ll1[8][NS1];
    __shared__ int ll2[8][NS2];

    const int lane = threadIdx.x & 31;
    const int wid  = threadIdx.x >> 5;
    const int q    = blockIdx.x * 8 + wid;
    const int b    = q >> 10;

    const int c1 = extract_list(g_mask1 + (size_t)q * NG, NGP, NS1, lane, ll1[wid]);
    const int c2 = extract_list(g_mask2 + (size_t)q * NG, NGP, NS2, lane, ll2[wid]);
    __syncwarp();

    if ((c1 >= NS1) && (c2 >= NS2)) {
        write_lists_padded(q, lane, ll1[wid], c1, ll2[wid], c2);
        if (lane == 0) g_filled[q] = 1;
    } else {
        if (lane == 0) {
            g_filled[q] = 0;
            const int pos = atomicAdd(&g_unf_cnt[b], 1);
            if (pos < SLOTCAP) g_unf[b][pos] = q;
        }
    }
}

// ---------------------------------------------------------------------------
// Kernel 3: tail masks, ballot-free, fully tile-parallel.
// Block = 256 thr = 16 slots x 16 words over the tail range [DPRE, NPTS).
// Grid = NBATCH x 64 slotblk x 96 wblk; blocks beyond the unfilled count exit.
// ---------------------------------------------------------------------------
__global__ __launch_bounds__(256) void mask_tail_kernel() {
    const int bid     = blockIdx.x;
    const int b       = bid / ((SLOTCAP / 16) * WBLK_T);
    const int r       = bid % ((SLOTCAP / 16) * WBLK_T);
    const int slotblk = r / WBLK_T;
    const int wblk    = r % WBLK_T;

    const int cnt = g_unf_cnt[b];
    if (slotblk * 16 >= cnt) return;

    const int tid  = threadIdx.x;
    const int slot = slotblk * 16 + (tid & 15);
    const bool valid = (slot < cnt) && (slot < SLOTCAP);
    const int q    = valid ? g_unf[b][slot] : (b << 10);
    const int word = NGP + wblk * 16 + (tid >> 4);

    int bb;
    const int fi = query_flat_index(q, bb);
    const float4* __restrict__ P4 = g_pts4 + (size_t)b * NPTS;
    const float4 qp = __ldg(P4 + fi);
    float r1sq, r2sq; radii(r1sq, r2sq);

    unsigned m1, m2;
    make_mask_word(P4, word * 32, qp, r1sq, r2sq, m1, m2);

    if (valid) {
        g_mask1[(size_t)q * NG + word] = m1;
        g_mask2[(size_t)q * NG + word] = m2;
    }
}

// ---------------------------------------------------------------------------
// Kernel 4: extract over full mask range for unfilled queries.
// ---------------------------------------------------------------------------
__global__ __launch_bounds__(256) void extract2_kernel() {
    __shared__ int ll1[8][NS1];
    __shared__ int ll2[8][NS2];

    const int lane = threadIdx.x & 31;
    const int wid  = threadIdx.x >> 5;
    const int q    = blockIdx.x * 8 + wid;
    if (g_filled[q]) return;

    const int c1 = extract_list(g_mask1 + (size_t)q * NG, NG, NS1, lane, ll1[wid]);
    const int c2 = extract_list(g_mask2 + (size_t)q * NG, NG, NS2, lane, ll2[wid]);
    __syncwarp();
    write_lists_padded(q, lane, ll1[wid], c1, ll2[wid], c2);
}

// ---------------------------------------------------------------------------
// Kernel 5: MLP (R3 version — measured 20.5us).
// ---------------------------------------------------------------------------
#define INVC 0.9999950000374997f

__device__ __forceinline__ void mlp_point(
    float gx, float gy, float gz, float qx, float qy, float qz,
    const float* __restrict__ sA, const float* __restrict__ scA, const float* __restrict__ biA,
    const float* __restrict__ sB, const float* __restrict__ scB, const float* __restrict__ biB,
    float f[32])
{
    const float x0 = gx - qx, x1 = gy - qy, x2 = gz - qz;
    float a[16];
#pragma unroll
    for (int o = 0; o < 16; o++) {
        const float* w = sA + o * 6;
        float y = x0 * w[0];
        y = fmaf(x1, w[1], y);
        y = fmaf(x2, w[2], y);
        y = fmaf(gx, w[3], y);
        y = fmaf(gy, w[4], y);
        y = fmaf(gz, w[5], y);
        a[o] = fmaxf(fmaf(y, scA[o], biA[o]), 0.0f);
    }
#pragma unroll
    for (int o = 0; o < 32; o++) {
        const float* w = sB + o * 16;
        float y = 0.0f;
#pragma unroll
        for (int c = 0; c < 16; c++) y = fmaf(a[c], w[c], y);
        f[o] = fmaxf(f[o], fmaxf(fmaf(y, scB[o], biB[o]), 0.0f));
    }
}

__device__ __forceinline__ void warp_max32(float f[32]) {
#pragma unroll
    for (int o = 0; o < 32; o++) {
        float v = f[o];
        v = fmaxf(v, __shfl_xor_sync(0xffffffffu, v, 16));
        v = fmaxf(v, __shfl_xor_sync(0xffffffffu, v, 8));
        v = fmaxf(v, __shfl_xor_sync(0xffffffffu, v, 4));
        v = fmaxf(v, __shfl_xor_sync(0xffffffffu, v, 2));
        v = fmaxf(v, __shfl_xor_sync(0xffffffffu, v, 1));
        f[o] = v;
    }
}

__global__ __launch_bounds__(256) void mlp_kernel(
    const float* __restrict__ w1a, const float* __restrict__ g1a, const float* __restrict__ b1a,
    const float* __restrict__ w1b, const float* __restrict__ g1b, const float* __restrict__ b1b,
    const float* __restrict__ w2a, const float* __restrict__ g2a, const float* __restrict__ b2a,
    const float* __restrict__ w2b, const float* __restrict__ g2b, const float* __restrict__ b2b,
    const float* __restrict__ w3,  const float* __restrict__ b3,
    float* __restrict__ out)
{
    __shared__ float s_w1a[96],  s_w2a[96];
    __shared__ float s_w1b[512], s_w2b[512];
    __shared__ float s_sc1a[16], s_bi1a[16], s_sc2a[16], s_bi2a[16];
    __shared__ float s_sc1b[32], s_bi1b[32], s_sc2b[32], s_bi2b[32];
    __shared__ float s_w3t[64 * 129];

    const int tid = threadIdx.x;
    for (int i = tid; i < 96; i += 256)  { s_w1a[i] = w1a[i]; s_w2a[i] = w2a[i]; }
    for (int i = tid; i < 512; i += 256) { s_w1b[i] = w1b[i]; s_w2b[i] = w2b[i]; }
    if (tid < 16) {
        s_sc1a[tid] = g1a[tid] * INVC; s_bi1a[tid] = b1a[tid];
        s_sc2a[tid] = g2a[tid] * INVC; s_bi2a[tid] = b2a[tid];
    } else if (tid < 48) {
        const int i = tid - 16;
        s_sc1b[i] = g1b[i] * INVC; s_bi1b[i] = b1b[i];
        s_sc2b[i] = g2b[i] * INVC; s_bi2b[i] = b2b[i];
    }
    const float4* __restrict__ w3v = (const float4*)w3;
    for (int i = tid; i < NOUT * 16; i += 256) {
        const float4 v = __ldg(w3v + i);
        const int o  = i >> 4;
        const int c4 = (i & 15) * 4;
        s_w3t[(c4 + 0) * 129 + o] = v.x;
        s_w3t[(c4 + 1) * 129 + o] = v.y;
        s_w3t[(c4 + 2) * 129 + o] = v.z;
        s_w3t[(c4 + 3) * 129 + o] = v.w;
    }
    __syncthreads();

    const int lane = tid & 31;
    const int wid  = tid >> 5;
    const int q    = blockIdx.x * 8 + wid;
    int b;
    const int fi = query_flat_index(q, b);

    const float4* __restrict__ P4 = g_pts4 + (size_t)b * NPTS;
    const float4 qp = __ldg(P4 + fi);
    const float qx = qp.x, qy = qp.y, qz = qp.z;

    const int* lst = g_lists + q * 96;
    const int i0 = __ldg(lst + lane);
    const int i1 = __ldg(lst + NS1 + lane);
    const int i2 = __ldg(lst + NS1 + 32 + lane);
    const float4 n0 = __ldg(P4 + i0);
    const float4 n1 = __ldg(P4 + i1);
    const float4 n2 = __ldg(P4 + i2);

    const size_t ob = (size_t)q * NOUT;
    float acc[4];
#pragma unroll
    for (int k = 0; k < 4; k++) acc[k] = __ldg(b3 + lane + 32 * k);

    {   // branch 1 (S=32)
        float f[32];
#pragma unroll
        for (int o = 0; o < 32; o++) f[o] = 0.0f;
        mlp_point(n0.x, n0.y, n0.z, qx, qy, qz, s_w1a, s_sc1a, s_bi1a, s_w1b, s_sc1b, s_bi1b, f);
        warp_max32(f);
#pragma unroll
        for (int k = 0; k < 4; k++) {
            const int o = lane + 32 * k;
            float a = acc[k];
#pragma unroll
            for (int c = 0; c < 32; c++) a = fmaf(f[c], s_w3t[c * 129 + o], a);
            acc[k] = a;
        }
    }
    {   // branch 2 (S=64)
        float f[32];
#pragma unroll
        for (int o = 0; o < 32; o++) f[o] = 0.0f;
        mlp_point(n1.x, n1.y, n1.z, qx, qy, qz, s_w2a, s_sc2a, s_bi2a, s_w2b, s_sc2b, s_bi2b, f);
        mlp_point(n2.x, n2.y, n2.z, qx, qy, qz, s_w2a, s_sc2a, s_bi2a, s_w2b, s_sc2b, s_bi2b, f);
        warp_max32(f);
#pragma unroll
        for (int k = 0; k < 4; k++) {
            const int o = lane + 32 * k;
            float a = acc[k];
#pragma unroll
            for (int c = 0; c < 32; c++) a = fmaf(f[c], s_w3t[(c + 32) * 129 + o], a);
            acc[k] = a;
        }
    }
#pragma unroll
    for (int k = 0; k < 4; k++) out[ob + lane + 32 * k] = acc[k];
}

extern "C" void kernel_launch(void* const* d_in, const int* in_sizes, int n_in,
                              void* d_out, int out_size) {
    const float* pts = (const float*)d_in[0];
    const float* w1a = (const float*)d_in[1];
    const float* g1a = (const float*)d_in[2];
    const float* b1a = (const float*)d_in[3];
    const float* w1b = (const float*)d_in[4];
    const float* g1b = (const float*)d_in[5];
    const float* b1b = (const float*)d_in[6];
    const float* w2a = (const float*)d_in[7];
    const float* g2a = (const float*)d_in[8];
    const float* b2a = (const float*)d_in[9];
    const float* w2b = (const float*)d_in[10];
    const float* g2b = (const float*)d_in[11];
    const float* b2b = (const float*)d_in[12];
    const float* w3  = (const float*)d_in[13];
    const float* b3  = (const float*)d_in[14];
    float* out = (float*)d_out;

    prep_kernel<<<NBATCH * NPTS / 256, 256>>>(pts);
    mask_prefix_kernel<<<128 * WBLK_P, 256>>>();
    extract1_kernel<<<NBATCH * NQ / 8, 256>>>();
    mask_tail_kernel<<<NBATCH * (SLOTCAP / 16) * WBLK_T, 256>>>();
    extract2_kernel<<<NBATCH * NQ / 8, 256>>>();
    mlp_kernel<<<NBATCH * NQ / 8, 256>>>(w1a, g1a, b1a, w1b, g1b, b1b,
                                         w2a, g2a, b2a, w2b, g2b, b2b, w3, b3, out);
}